// round 1
// baseline (speedup 1.0000x reference)
#include <cuda_runtime.h>
#include <math.h>

// NodeConv decomposition:
//   xs = [x | gs]  (133)
//   y_neg[n]  = xs[n] @ W_neg[0:133] + b_neg            (per NODE, not per edge)
//   out[n]    = elu(xs[n] @ W_root + b_root)
//   per edge e: out[dst] += elu(y_neg[src] + ea[e] @ W_neg[133:139])

#define NMAX 100000

__device__ float g_yneg[(size_t)NMAX * 128];
__device__ int g_is64;

__device__ __forceinline__ float eluf(float v) {
    return v > 0.0f ? v : expm1f(v);
}

// ---------------------------------------------------------------------------
// Detect whether edge_index is int64 (JAX x64 on) or int32 (JAX default).
// Values are in [0, 1e5): if stored as int64, every odd 32-bit word is the
// zero high-half. Probability of 1024 random int32 indices all being zero ~ 0.
// ---------------------------------------------------------------------------
__global__ void detect_kernel(const int* __restrict__ ei32, int nwords) {
    if (threadIdx.x == 0 && blockIdx.x == 0) {
        int lim = nwords < 2048 ? nwords : 2048;
        int odd_nz = 0;
        for (int i = 1; i < lim; i += 2) odd_nz += (ei32[i] != 0);
        g_is64 = (odd_nz == 0) ? 1 : 0;
    }
}

// ---------------------------------------------------------------------------
// K1: fused node GEMM. Tile = 64 nodes x 256 outputs (128 y_neg | 128 root).
// A-tile (64x133) staged in smem; W rows streamed via __ldg (fits in L1 after
// first pass; L1 persists across CTAs within a launch). 8x8 register microtile.
// ---------------------------------------------------------------------------
__global__ __launch_bounds__(256, 2)
void node_gemm_kernel(const float* __restrict__ x,
                      const float* __restrict__ gs,
                      const float* __restrict__ W_neg,   // [139][128]
                      const float* __restrict__ b_neg,   // [128]
                      const float* __restrict__ W_root,  // [133][128]
                      const float* __restrict__ b_root,  // [128]
                      float* __restrict__ out,
                      int N)
{
    __shared__ float As[64][136];   // 133 used, padded
    const int tid = threadIdx.x;
    const int n0 = blockIdx.x * 64;

    for (int i = tid; i < 64 * 133; i += 256) {
        int m = i / 133;
        int k = i - m * 133;
        int n = n0 + m;
        float v = 0.0f;
        if (n < N) v = (k < 128) ? x[(size_t)n * 128 + k]
                                 : gs[(size_t)n * 5 + (k - 128)];
        As[m][k] = v;
    }
    __syncthreads();

    const int c = tid & 31;   // column group (8 cols each)
    const int r = tid >> 5;   // row group = warp id (8 rows each)
    const bool isRoot = (c >= 16);
    const float* Wsel = isRoot ? W_root : W_neg;
    const float* bsel = isRoot ? b_root : b_neg;
    const int cb = (isRoot ? (c - 16) : c) * 8;

    float acc[8][8];
#pragma unroll
    for (int j = 0; j < 8; j++) {
        float bv = __ldg(bsel + cb + j);
#pragma unroll
        for (int i = 0; i < 8; i++) acc[i][j] = bv;
    }

#pragma unroll 2
    for (int k = 0; k < 133; k++) {
        float4 b0 = __ldg((const float4*)(Wsel + (size_t)k * 128 + cb));
        float4 b1 = __ldg((const float4*)(Wsel + (size_t)k * 128 + cb + 4));
        float a[8];
#pragma unroll
        for (int i = 0; i < 8; i++) a[i] = As[r * 8 + i][k];
#pragma unroll
        for (int i = 0; i < 8; i++) {
            acc[i][0] += a[i] * b0.x;
            acc[i][1] += a[i] * b0.y;
            acc[i][2] += a[i] * b0.z;
            acc[i][3] += a[i] * b0.w;
            acc[i][4] += a[i] * b1.x;
            acc[i][5] += a[i] * b1.y;
            acc[i][6] += a[i] * b1.z;
            acc[i][7] += a[i] * b1.w;
        }
    }

#pragma unroll
    for (int i = 0; i < 8; i++) {
        int n = n0 + r * 8 + i;
        if (n < N) {
            if (isRoot) {
                float4 o0, o1;
                o0.x = eluf(acc[i][0]); o0.y = eluf(acc[i][1]);
                o0.z = eluf(acc[i][2]); o0.w = eluf(acc[i][3]);
                o1.x = eluf(acc[i][4]); o1.y = eluf(acc[i][5]);
                o1.z = eluf(acc[i][6]); o1.w = eluf(acc[i][7]);
                *((float4*)(out + (size_t)n * 128 + cb))     = o0;
                *((float4*)(out + (size_t)n * 128 + cb + 4)) = o1;
            } else {
                float4 o0 = make_float4(acc[i][0], acc[i][1], acc[i][2], acc[i][3]);
                float4 o1 = make_float4(acc[i][4], acc[i][5], acc[i][6], acc[i][7]);
                *((float4*)(g_yneg + (size_t)n * 128 + cb))     = o0;
                *((float4*)(g_yneg + (size_t)n * 128 + cb + 4)) = o1;
            }
        }
    }
}

// ---------------------------------------------------------------------------
// K2: one warp per edge (grid-strided). Gather y_neg[src] (L2-resident),
// add edge_attr @ W2 (W2 kept in registers: 6 float4 per lane), ELU,
// scatter-add 128 floats into out[dst].
// ---------------------------------------------------------------------------
__global__ __launch_bounds__(256)
void edge_kernel(const void* __restrict__ ei_raw,
                 const float* __restrict__ edge_attr,   // [E][6]
                 const float* __restrict__ W_neg,       // [139][128]
                 float* __restrict__ out,
                 int E)
{
    const int lane  = threadIdx.x & 31;
    const int warp  = blockIdx.x * (blockDim.x >> 5) + (threadIdx.x >> 5);
    const int nwarp = gridDim.x * (blockDim.x >> 5);
    const int is64  = g_is64;
    const long long* ei64 = (const long long*)ei_raw;
    const int*       ei32 = (const int*)ei_raw;

    float4 w2[6];
#pragma unroll
    for (int d = 0; d < 6; d++)
        w2[d] = __ldg((const float4*)(W_neg + (size_t)(133 + d) * 128) + lane);

    for (int e = warp; e < E; e += nwarp) {
        int dst, src;
        if (is64) {
            dst = (int)__ldg(ei64 + e);
            src = (int)__ldg(ei64 + (size_t)E + e);
        } else {
            dst = __ldg(ei32 + e);
            src = __ldg(ei32 + (size_t)E + e);
        }
        const float* ea = edge_attr + (size_t)e * 6;
        float a0 = __ldg(ea + 0), a1 = __ldg(ea + 1), a2 = __ldg(ea + 2);
        float a3 = __ldg(ea + 3), a4 = __ldg(ea + 4), a5 = __ldg(ea + 5);

        float4 v = __ldg((const float4*)(g_yneg + (size_t)src * 128) + lane);

        v.x += a0 * w2[0].x + a1 * w2[1].x + a2 * w2[2].x
             + a3 * w2[3].x + a4 * w2[4].x + a5 * w2[5].x;
        v.y += a0 * w2[0].y + a1 * w2[1].y + a2 * w2[2].y
             + a3 * w2[3].y + a4 * w2[4].y + a5 * w2[5].y;
        v.z += a0 * w2[0].z + a1 * w2[1].z + a2 * w2[2].z
             + a3 * w2[3].z + a4 * w2[4].z + a5 * w2[5].z;
        v.w += a0 * w2[0].w + a1 * w2[1].w + a2 * w2[2].w
             + a3 * w2[3].w + a4 * w2[4].w + a5 * w2[5].w;

        v.x = eluf(v.x);
        v.y = eluf(v.y);
        v.z = eluf(v.z);
        v.w = eluf(v.w);

        float* o = out + (size_t)dst * 128 + lane * 4;
        atomicAdd(o + 0, v.x);
        atomicAdd(o + 1, v.y);
        atomicAdd(o + 2, v.z);
        atomicAdd(o + 3, v.w);
    }
}

// ---------------------------------------------------------------------------
extern "C" void kernel_launch(void* const* d_in, const int* in_sizes, int n_in,
                              void* d_out, int out_size)
{
    const float* x      = (const float*)d_in[0];
    const void*  ei     = d_in[1];
    const float* eattr  = (const float*)d_in[2];
    const float* gs     = (const float*)d_in[3];
    const float* W_neg  = (const float*)d_in[4];
    const float* b_neg  = (const float*)d_in[5];
    const float* W_root = (const float*)d_in[6];
    const float* b_root = (const float*)d_in[7];
    float* out = (float*)d_out;

    const int N = in_sizes[0] / 128;   // 100000
    const int E = in_sizes[2] / 6;     // 1600000

    detect_kernel<<<1, 32>>>((const int*)ei, in_sizes[1]);

    node_gemm_kernel<<<(N + 63) / 64, 256>>>(x, gs, W_neg, b_neg,
                                             W_root, b_root, out, N);

    edge_kernel<<<592, 256>>>(ei, eattr, W_neg, out, E);
}

// round 2
// speedup vs baseline: 1.1756x; 1.1756x over previous
#include <cuda_runtime.h>
#include <math.h>

// NodeConv:
//   xs = [x | gs]  (133)
//   y_neg[n]  = xs[n] @ W_neg[0:133] + b_neg           (per NODE)
//   out[n]    = elu(xs[n] @ W_root + b_root)
//   out[dst] += sum_{e: dst(e)=dst} elu(y_neg[src(e)] + ea[e] @ W_neg[133:139])
//
// Scatter converted to gather via per-call CSR build (counting sort by dst):
// no float atomics at all.

#define NMAX 100000
#define EMAX 1600000

__device__ float g_yneg[(size_t)NMAX * 128];
__device__ int   g_count[NMAX];
__device__ int   g_offset[NMAX + 1];
__device__ int   g_cursor[NMAX];
__device__ int   g_eid[EMAX];
__device__ int   g_is64;

__device__ __forceinline__ float eluf(float v) {
    return v > 0.0f ? v : expm1f(v);
}

__device__ __forceinline__ int load_idx(const void* ei, int is64, size_t pos) {
    return is64 ? (int)__ldg((const long long*)ei + pos)
                : __ldg((const int*)ei + pos);
}

// ---------------------------------------------------------------------------
// Prep: block 0 detects int64-vs-int32 (parallel), all blocks zero g_count.
// ---------------------------------------------------------------------------
__global__ void prep_kernel(const int* __restrict__ ei32, int nwords, int N) {
    if (blockIdx.x == 0) {
        // int64 indices < 1e5 -> every odd 32-bit word is zero.
        int nz = 0;
        for (int i = 1 + 2 * threadIdx.x; i < min(nwords, 4096); i += 2 * blockDim.x)
            nz |= (ei32[i] != 0);
        int any = __syncthreads_or(nz);
        if (threadIdx.x == 0) g_is64 = any ? 0 : 1;
    }
    for (int i = blockIdx.x * blockDim.x + threadIdx.x; i < N;
         i += gridDim.x * blockDim.x)
        g_count[i] = 0;
}

// ---------------------------------------------------------------------------
// Histogram of dst.
// ---------------------------------------------------------------------------
__global__ void hist_kernel(const void* __restrict__ ei, int E) {
    const int is64 = g_is64;
    for (int e = blockIdx.x * blockDim.x + threadIdx.x; e < E;
         e += gridDim.x * blockDim.x) {
        int dst = load_idx(ei, is64, e);
        atomicAdd(&g_count[dst], 1);
    }
}

// ---------------------------------------------------------------------------
// Single-block exclusive scan of g_count (N up to 100k) -> g_offset, g_cursor.
// ---------------------------------------------------------------------------
__global__ __launch_bounds__(1024)
void scan_kernel(int N, int E) {
    __shared__ int carry;
    __shared__ int wsum[32];
    const int tid = threadIdx.x;
    const int lane = tid & 31, w = tid >> 5;
    if (tid == 0) carry = 0;
    __syncthreads();

    for (int base = 0; base < N; base += 1024) {
        int i = base + tid;
        int c = (i < N) ? g_count[i] : 0;
        int v = c;
#pragma unroll
        for (int o = 1; o < 32; o <<= 1) {
            int t = __shfl_up_sync(0xffffffffu, v, o);
            if (lane >= o) v += t;
        }
        if (lane == 31) wsum[w] = v;
        __syncthreads();
        if (w == 0) {
            int s = wsum[lane];
#pragma unroll
            for (int o = 1; o < 32; o <<= 1) {
                int t = __shfl_up_sync(0xffffffffu, s, o);
                if (lane >= o) s += t;
            }
            wsum[lane] = s;
        }
        __syncthreads();
        int wbase = (w == 0) ? 0 : wsum[w - 1];
        int excl = carry + wbase + v - c;
        if (i < N) {
            g_offset[i] = excl;
            g_cursor[i] = excl;
        }
        int total = wsum[31];
        __syncthreads();
        if (tid == 0) carry += total;
        __syncthreads();
    }
    if (tid == 0) g_offset[N] = E;
}

// ---------------------------------------------------------------------------
// Scatter edge ids into CSR buckets.
// ---------------------------------------------------------------------------
__global__ void scatter_kernel(const void* __restrict__ ei, int E) {
    const int is64 = g_is64;
    for (int e = blockIdx.x * blockDim.x + threadIdx.x; e < E;
         e += gridDim.x * blockDim.x) {
        int dst = load_idx(ei, is64, e);
        int pos = atomicAdd(&g_cursor[dst], 1);
        g_eid[pos] = e;
    }
}

// ---------------------------------------------------------------------------
// K1: fused node GEMM. Tile = 64 nodes x 256 outputs (128 y_neg | 128 root).
// ---------------------------------------------------------------------------
__global__ __launch_bounds__(256, 2)
void node_gemm_kernel(const float* __restrict__ x,
                      const float* __restrict__ gs,
                      const float* __restrict__ W_neg,   // [139][128]
                      const float* __restrict__ b_neg,
                      const float* __restrict__ W_root,  // [133][128]
                      const float* __restrict__ b_root,
                      float* __restrict__ out,
                      int N)
{
    __shared__ float As[64][136];
    const int tid = threadIdx.x;
    const int n0 = blockIdx.x * 64;

    for (int i = tid; i < 64 * 133; i += 256) {
        int m = i / 133;
        int k = i - m * 133;
        int n = n0 + m;
        float v = 0.0f;
        if (n < N) v = (k < 128) ? x[(size_t)n * 128 + k]
                                 : gs[(size_t)n * 5 + (k - 128)];
        As[m][k] = v;
    }
    __syncthreads();

    const int c = tid & 31;
    const int r = tid >> 5;
    const bool isRoot = (c >= 16);
    const float* Wsel = isRoot ? W_root : W_neg;
    const float* bsel = isRoot ? b_root : b_neg;
    const int cb = (isRoot ? (c - 16) : c) * 8;

    float acc[8][8];
#pragma unroll
    for (int j = 0; j < 8; j++) {
        float bv = __ldg(bsel + cb + j);
#pragma unroll
        for (int i = 0; i < 8; i++) acc[i][j] = bv;
    }

#pragma unroll 2
    for (int k = 0; k < 133; k++) {
        float4 b0 = __ldg((const float4*)(Wsel + (size_t)k * 128 + cb));
        float4 b1 = __ldg((const float4*)(Wsel + (size_t)k * 128 + cb + 4));
        float a[8];
#pragma unroll
        for (int i = 0; i < 8; i++) a[i] = As[r * 8 + i][k];
#pragma unroll
        for (int i = 0; i < 8; i++) {
            acc[i][0] += a[i] * b0.x;
            acc[i][1] += a[i] * b0.y;
            acc[i][2] += a[i] * b0.z;
            acc[i][3] += a[i] * b0.w;
            acc[i][4] += a[i] * b1.x;
            acc[i][5] += a[i] * b1.y;
            acc[i][6] += a[i] * b1.z;
            acc[i][7] += a[i] * b1.w;
        }
    }

#pragma unroll
    for (int i = 0; i < 8; i++) {
        int n = n0 + r * 8 + i;
        if (n < N) {
            if (isRoot) {
                float4 o0, o1;
                o0.x = eluf(acc[i][0]); o0.y = eluf(acc[i][1]);
                o0.z = eluf(acc[i][2]); o0.w = eluf(acc[i][3]);
                o1.x = eluf(acc[i][4]); o1.y = eluf(acc[i][5]);
                o1.z = eluf(acc[i][6]); o1.w = eluf(acc[i][7]);
                *((float4*)(out + (size_t)n * 128 + cb))     = o0;
                *((float4*)(out + (size_t)n * 128 + cb + 4)) = o1;
            } else {
                *((float4*)(g_yneg + (size_t)n * 128 + cb)) =
                    make_float4(acc[i][0], acc[i][1], acc[i][2], acc[i][3]);
                *((float4*)(g_yneg + (size_t)n * 128 + cb + 4)) =
                    make_float4(acc[i][4], acc[i][5], acc[i][6], acc[i][7]);
            }
        }
    }
}

// ---------------------------------------------------------------------------
// Gather: one warp per node. Accumulate elu(y_neg[src] + ea@W2) over the
// node's CSR edge list in registers, add to out[n] (which holds the root
// term). No atomics.
// ---------------------------------------------------------------------------
__global__ __launch_bounds__(256)
void gather_kernel(const void* __restrict__ ei,
                   const float* __restrict__ edge_attr,  // [E][6]
                   const float* __restrict__ W_neg,      // [139][128]
                   float* __restrict__ out,
                   int N, int E)
{
    const int lane  = threadIdx.x & 31;
    const int warp  = blockIdx.x * (blockDim.x >> 5) + (threadIdx.x >> 5);
    const int nwarp = gridDim.x * (blockDim.x >> 5);
    const int is64  = g_is64;

    float4 w2[6];
#pragma unroll
    for (int d = 0; d < 6; d++)
        w2[d] = __ldg((const float4*)(W_neg + (size_t)(133 + d) * 128) + lane);

    for (int n = warp; n < N; n += nwarp) {
        const int beg = __ldg(&g_offset[n]);
        const int end = __ldg(&g_offset[n + 1]);
        float4 acc = make_float4(0.f, 0.f, 0.f, 0.f);

        int j = beg;
        for (; j + 1 < end; j += 2) {
            // two independent edges -> MLP on the eid->src->y_neg chain
            int e0 = __ldg(&g_eid[j]);
            int e1 = __ldg(&g_eid[j + 1]);
            int s0 = load_idx(ei, is64, (size_t)E + e0);
            int s1 = load_idx(ei, is64, (size_t)E + e1);
            float4 v0 = __ldg((const float4*)(g_yneg + (size_t)s0 * 128) + lane);
            float4 v1 = __ldg((const float4*)(g_yneg + (size_t)s1 * 128) + lane);
            const float* ea0 = edge_attr + (size_t)e0 * 6;
            const float* ea1 = edge_attr + (size_t)e1 * 6;
#pragma unroll
            for (int d = 0; d < 6; d++) {
                float a0 = __ldg(ea0 + d);
                float a1 = __ldg(ea1 + d);
                v0.x += a0 * w2[d].x; v0.y += a0 * w2[d].y;
                v0.z += a0 * w2[d].z; v0.w += a0 * w2[d].w;
                v1.x += a1 * w2[d].x; v1.y += a1 * w2[d].y;
                v1.z += a1 * w2[d].z; v1.w += a1 * w2[d].w;
            }
            acc.x += eluf(v0.x) + eluf(v1.x);
            acc.y += eluf(v0.y) + eluf(v1.y);
            acc.z += eluf(v0.z) + eluf(v1.z);
            acc.w += eluf(v0.w) + eluf(v1.w);
        }
        if (j < end) {
            int e0 = __ldg(&g_eid[j]);
            int s0 = load_idx(ei, is64, (size_t)E + e0);
            float4 v0 = __ldg((const float4*)(g_yneg + (size_t)s0 * 128) + lane);
            const float* ea0 = edge_attr + (size_t)e0 * 6;
#pragma unroll
            for (int d = 0; d < 6; d++) {
                float a0 = __ldg(ea0 + d);
                v0.x += a0 * w2[d].x; v0.y += a0 * w2[d].y;
                v0.z += a0 * w2[d].z; v0.w += a0 * w2[d].w;
            }
            acc.x += eluf(v0.x);
            acc.y += eluf(v0.y);
            acc.z += eluf(v0.z);
            acc.w += eluf(v0.w);
        }

        float4* o = (float4*)(out + (size_t)n * 128) + lane;
        float4 cur = *o;
        cur.x += acc.x; cur.y += acc.y; cur.z += acc.z; cur.w += acc.w;
        *o = cur;
    }
}

// ---------------------------------------------------------------------------
extern "C" void kernel_launch(void* const* d_in, const int* in_sizes, int n_in,
                              void* d_out, int out_size)
{
    const float* x      = (const float*)d_in[0];
    const void*  ei     = d_in[1];
    const float* eattr  = (const float*)d_in[2];
    const float* gs     = (const float*)d_in[3];
    const float* W_neg  = (const float*)d_in[4];
    const float* b_neg  = (const float*)d_in[5];
    const float* W_root = (const float*)d_in[6];
    const float* b_root = (const float*)d_in[7];
    float* out = (float*)d_out;

    const int N = in_sizes[0] / 128;   // 100000
    const int E = in_sizes[2] / 6;     // 1600000

    prep_kernel<<<128, 256>>>((const int*)ei, in_sizes[1], N);
    hist_kernel<<<1184, 256>>>(ei, E);
    scan_kernel<<<1, 1024>>>(N, E);
    scatter_kernel<<<1184, 256>>>(ei, E);

    node_gemm_kernel<<<(N + 63) / 64, 256>>>(x, gs, W_neg, b_neg,
                                             W_root, b_root, out, N);

    gather_kernel<<<(N * 32 + 255) / 256, 256>>>(ei, eattr, W_neg, out, N, E);
}